// round 1
// baseline (speedup 1.0000x reference)
#include <cuda_runtime.h>
#include <cstdint>

// E2M1 block quantizer.
// Layout (one warp = 4 quant-blocks, one thread = 4 contiguous elements):
//   thread t handles elements [4t, 4t+4); quant block id = t >> 3 (8 lanes/block).
// Outputs concatenated as float32 in reference-tuple order:
//   [0, n)          deq_weight
//   [n, 2n)         encoded (0..15)
//   [2n, 2n+nb)     e8m0 scale + 127 (0..255)
//   [2n+nb, 2n+2nb) eps_base = 0.5*tanh(eps_param)

__global__ __launch_bounds__(256) void e2m1_quant_kernel(
    const float* __restrict__ w,
    const float* __restrict__ eps_param,
    float* __restrict__ deq,
    float* __restrict__ enc,
    float* __restrict__ scl,
    float* __restrict__ epsb,
    int n_elem)
{
    const int t = blockIdx.x * blockDim.x + threadIdx.x;
    const long base = (long)t * 4;
    if (base >= (long)n_elem) return;

    const int blk = t >> 3;  // 32-element quant block index

    float4 wv = *reinterpret_cast<const float4*>(w + base);

    // ---- block amax: abs-bits compare as unsigned for finite floats ----
    unsigned am = __float_as_uint(fabsf(wv.x));
    am = max(am, __float_as_uint(fabsf(wv.y)));
    am = max(am, __float_as_uint(fabsf(wv.z)));
    am = max(am, __float_as_uint(fabsf(wv.w)));
    am = max(am, (unsigned)__shfl_xor_sync(0xffffffffu, (int)am, 1));
    am = max(am, (unsigned)__shfl_xor_sync(0xffffffffu, (int)am, 2));
    am = max(am, (unsigned)__shfl_xor_sync(0xffffffffu, (int)am, 4));
    const float amax = __uint_as_float(am);

    // ---- e8m0 = clamp(ceil(log2(amax/6)), -127, ...) computed exactly ----
    const float descale = amax / 6.0f;
    int e8;
    if (descale == 0.0f) {
        e8 = -127;
    } else {
        int e;
        float m = frexpf(descale, &e);   // descale = m * 2^e, m in [0.5, 1)
        e8 = (m == 0.5f) ? (e - 1) : e;  // exact ceil(log2(descale))
        if (e8 < -127) e8 = -127;
    }
    const float scale     = ldexpf(1.0f,  e8);
    const float inv_scale = ldexpf(1.0f, -e8);

    // ---- block epsilon ----
    const float eps = 0.5f * tanhf(eps_param[blk]);

    // ---- per-element encode + dequant ----
    float4 dv, ev;
    #pragma unroll
    for (int i = 0; i < 4; i++) {
        const float wx = (i == 0) ? wv.x : (i == 1) ? wv.y : (i == 2) ? wv.z : wv.w;
        const float wn = wx * inv_scale;            // exact: scale is 2^k
        const float as = fmaxf(fabsf(wn) + eps, 0.0f);
        const bool  neg = !(wn > 0.0f);             // matches floor((2-sign)/2)
        int ord = (as > 0.25f) + (as > 0.75f) + (as > 1.25f) + (as > 1.75f)
                + (as > 2.5f)  + (as > 3.5f)  + (as > 5.0f);
        float mant = (ord <= 4) ? 0.5f * (float)ord
                   : (ord == 5) ? 3.0f : (ord == 6) ? 4.0f : 6.0f;
        const float dq = (neg ? -mant : mant) * scale;
        const float ec = (float)(ord + (neg ? 8 : 0));
        if (i == 0) { dv.x = dq; ev.x = ec; }
        else if (i == 1) { dv.y = dq; ev.y = ec; }
        else if (i == 2) { dv.z = dq; ev.z = ec; }
        else { dv.w = dq; ev.w = ec; }
    }

    *reinterpret_cast<float4*>(deq + base) = dv;
    if (enc) *reinterpret_cast<float4*>(enc + base) = ev;

    if ((t & 7) == 0 && scl) {
        scl[blk]  = (float)(e8 + 127);
        epsb[blk] = eps;
    }
}

extern "C" void kernel_launch(void* const* d_in, const int* in_sizes, int n_in,
                              void* d_out, int out_size) {
    const float* w  = (const float*)d_in[0];   // weight_fp [out_f*in_f]
    const float* ep = (const float*)d_in[1];   // eps_param [out_f*in_f/32]
    const int n  = in_sizes[0];
    const int nb = (n_in > 1) ? in_sizes[1] : n / 32;

    float* out  = (float*)d_out;
    float* deq  = out;
    float* enc  = nullptr;
    float* scl  = nullptr;
    float* epsb = nullptr;

    const long total_all = 2L * n + 2L * nb;
    if ((long)out_size >= total_all) {
        enc  = out + n;
        scl  = out + 2L * n;
        epsb = scl + nb;
    } else if ((long)out_size >= 2L * n) {
        enc = out + n;
    }

    const int threads = 256;
    const int nthreads_total = n / 4;
    const int ctas = (nthreads_total + threads - 1) / threads;
    e2m1_quant_kernel<<<ctas, threads>>>(w, ep, deq, enc, scl, epsb, n);
}

// round 11
// speedup vs baseline: 1.3593x; 1.3593x over previous
#include <cuda_runtime.h>
#include <cstdint>

// E2M1 block quantizer — software bit-trick encode (no fp4 HW cvt on this target).
// One thread = 4 contiguous elements; 8 lanes share a 32-element quant block.
// Output layout (float32, reference-tuple order):
//   [0, n)          deq_weight
//   [n, 2n)         encoded (0..15)
//   [2n, 2n+nb)     e8m0 scale + 127
//   [2n+nb, 2n+2nb) eps_base = 0.5*tanh(eps_param)

__global__ __launch_bounds__(256) void e2m1_quant_kernel(
    const float* __restrict__ w,
    const float* __restrict__ eps_param,
    float* __restrict__ deq,
    float* __restrict__ enc,
    float* __restrict__ scl,
    float* __restrict__ epsb,
    int n_elem)
{
    const int t = blockIdx.x * blockDim.x + threadIdx.x;
    const long base = (long)t * 4;
    if (base >= (long)n_elem) return;

    const int blk = t >> 3;  // 32-element quant block index

    const float4 wv = *reinterpret_cast<const float4*>(w + base);

    // ---- block amax: FMNMX with |.| operand modifiers + 3 butterfly levels ----
    float am = fmaxf(fmaxf(fabsf(wv.x), fabsf(wv.y)),
                     fmaxf(fabsf(wv.z), fabsf(wv.w)));
    am = fmaxf(am, __shfl_xor_sync(0xffffffffu, am, 1));
    am = fmaxf(am, __shfl_xor_sync(0xffffffffu, am, 2));
    am = fmaxf(am, __shfl_xor_sync(0xffffffffu, am, 4));

    // ---- e8m0: k = e8+127 = exp_field(descale) + (frac != 0)  (== ceil(log2)) ----
    const float descale = am * 0.16666667f;  // 1/6; ulp-level diff vs div: ~0 blocks flip
    const unsigned db = __float_as_uint(descale);
    const int k = (int)(db >> 23) + ((db & 0x7FFFFFu) ? 1 : 0);  // db==0 -> k=0 (e8=-127)
    const float scale     = __uint_as_float((unsigned)k << 23);
    const float inv_scale = __uint_as_float((unsigned)(254 - k) << 23);

    // ---- block epsilon: fast tanh via MUFU.EX2 (~2e-7 rel; MUFU.TANH too coarse) ----
    const float x2 = 2.0f * eps_param[blk];
    const float et = __expf(x2);
    const float eps = 0.5f * (et - 1.0f) * __fdividef(1.0f, et + 1.0f);

    // ---- per-element encode + dequant ----
    float dq[4], ef[4];
    const float win[4] = {wv.x, wv.y, wv.z, wv.w};
    #pragma unroll
    for (int i = 0; i < 4; i++) {
        const float a = win[i];
        // s = max(|a|*2^-e8 + eps, 0); pow2 multiply exact -> FFMA == ref two-step
        const float s = fmaxf(fmaf(fabsf(a), inv_scale, eps), 0.0f);

        // normal region: clamp to [1,6], round to 1 mantissa bit (grid 1,1.5,2,3,4,6;
        // midpoint thresholds 1.25/1.75/2.5/3.5/5 match the reference bounds)
        const float sc = fminf(fmaxf(s, 1.0f), 6.0f);
        const unsigned r = (__float_as_uint(sc) + 0x00200000u) & 0xFFC00000u;

        const bool pbig = (s > 0.75f);   // -> q >= 1
        const bool psml = (s > 0.25f);   // -> q = 0.5 in sub-1 region

        const unsigned qb = pbig ? r : (psml ? 0x3F000000u : 0u);
        const int ord = pbig ? ((int)(r >> 22) - 252) : (psml ? 1 : 0);

        const bool pneg = !(a > 0.0f);   // matches floor((2-sign)/2), incl. zero
        ef[i] = (float)(pneg ? ord + 8 : ord);

        const float dv = __uint_as_float(qb) * scale;  // exact pow2 scaling
        dq[i] = pneg ? -dv : dv;
    }

    *reinterpret_cast<float4*>(deq + base) = make_float4(dq[0], dq[1], dq[2], dq[3]);
    if (enc)
        *reinterpret_cast<float4*>(enc + base) = make_float4(ef[0], ef[1], ef[2], ef[3]);

    if ((t & 7) == 0 && scl) {
        scl[blk]  = (float)k;
        epsb[blk] = eps;
    }
}

extern "C" void kernel_launch(void* const* d_in, const int* in_sizes, int n_in,
                              void* d_out, int out_size) {
    const float* w  = (const float*)d_in[0];   // weight_fp [out_f*in_f]
    const float* ep = (const float*)d_in[1];   // eps_param [out_f*in_f/32]
    const int n  = in_sizes[0];
    const int nb = (n_in > 1) ? in_sizes[1] : n / 32;

    float* out  = (float*)d_out;
    float* deq  = out;
    float* enc  = nullptr;
    float* scl  = nullptr;
    float* epsb = nullptr;

    const long total_all = 2L * n + 2L * nb;
    if ((long)out_size >= total_all) {
        enc  = out + n;
        scl  = out + 2L * n;
        epsb = scl + nb;
    } else if ((long)out_size >= 2L * n) {
        enc = out + n;
    }

    const int threads = 256;
    const int nthreads_total = n / 4;
    const int ctas = (nthreads_total + threads - 1) / threads;
    e2m1_quant_kernel<<<ctas, threads>>>(w, ep, deq, enc, scl, epsb, n);
}